// round 12
// baseline (speedup 1.0000x reference)
#include <cuda_runtime.h>
#include <cuda_bf16.h>
#include <cuda_fp16.h>
#include <cstdint>

// ---------------------------------------------------------------------------
// RecurrentRetention: B=16, T=2048, D=256, gamma=0.9
//   vsum[b,t] = x[b,t,:].rowsum(Wv);  y[t,e] = sum_b vsum[b,t]*x[b,t,e]
//   c = y @ Wk;  r[t] = 0.9 r[t-1] + c[t] (exact 2-phase scan) -> S
//   out[b,q,p] = S[8p+(q>>8), q&255] * (x @ Wq)[b,q,p]
// cgemm: bf16 3-pass split (accuracy -> scan).  qgemm: fp16 1-pass, register
// double-buffered; A is read as fp32 and converted fp32->fp16 in-register
// (no g_xh intermediate).  Scan: exact 2-phase (A: tile scan+carry, BC:
// self-computed carry prefix + fixup) — measured faster than windowed.
// ---------------------------------------------------------------------------

#define Bsz 16
#define T   2048
#define D   256
#define LTILE 8
#define NTILE (T / LTILE)             // 256
#define GL 0.43046721f                // 0.9^8

__device__ float g_wvsum[D];
__device__ float g_c[T * D];
__device__ float g_S[T * D];
__device__ float g_carry[NTILE * D];
__device__ __nv_bfloat16 g_yh[T * D];
__device__ __nv_bfloat16 g_yl[T * D];
__device__ __half        g_wqh[D * D];  // Wq^T fp16, [n][k]
__device__ __nv_bfloat16 g_bkh[D * D];  // Wk^T hi bf16
__device__ __nv_bfloat16 g_bkl[D * D];

__device__ __forceinline__ uint32_t smem_u32(const void* p) {
    uint32_t a;
    asm("{ .reg .u64 t; cvta.to.shared.u64 t, %1; cvt.u32.u64 %0, t; }" : "=r"(a) : "l"(p));
    return a;
}
__device__ __forceinline__ void ldm_x4(uint32_t* r, uint32_t addr) {
    asm volatile("ldmatrix.sync.aligned.m8n8.x4.shared.b16 {%0,%1,%2,%3}, [%4];"
        : "=r"(r[0]), "=r"(r[1]), "=r"(r[2]), "=r"(r[3]) : "r"(addr));
}
__device__ __forceinline__ void ldm_x2(uint32_t* r, uint32_t addr) {
    asm volatile("ldmatrix.sync.aligned.m8n8.x2.shared.b16 {%0,%1}, [%2];"
        : "=r"(r[0]), "=r"(r[1]) : "r"(addr));
}
__device__ __forceinline__ void mma_bf16(float* c, const uint32_t* a, const uint32_t* b) {
    asm volatile(
        "mma.sync.aligned.m16n8k16.row.col.f32.bf16.bf16.f32 "
        "{%0,%1,%2,%3}, {%4,%5,%6,%7}, {%8,%9}, {%0,%1,%2,%3};"
        : "+f"(c[0]), "+f"(c[1]), "+f"(c[2]), "+f"(c[3])
        : "r"(a[0]), "r"(a[1]), "r"(a[2]), "r"(a[3]), "r"(b[0]), "r"(b[1]));
}
__device__ __forceinline__ void mma_fp16(float* c, const uint32_t* a, const uint32_t* b) {
    asm volatile(
        "mma.sync.aligned.m16n8k16.row.col.f32.f16.f16.f32 "
        "{%0,%1,%2,%3}, {%4,%5,%6,%7}, {%8,%9}, {%0,%1,%2,%3};"
        : "+f"(c[0]), "+f"(c[1]), "+f"(c[2]), "+f"(c[3])
        : "r"(a[0]), "r"(a[1]), "r"(a[2]), "r"(a[3]), "r"(b[0]), "r"(b[1]));
}
__device__ __forceinline__ uint32_t pack_h2(float a, float b) {
    __half2 h = __floats2half2_rn(a, b);
    return *(uint32_t*)&h;
}

// ======================= prep: wvsum + weight transpose-splits =============
__global__ void prep_kernel(const float* __restrict__ Wq, const float* __restrict__ Wk,
                            const float* __restrict__ Wv) {
    int bx = blockIdx.x, tid = threadIdx.x;
    if (bx < 256) {                       // Wq^T -> fp16
        int k = bx, n = tid;
        g_wqh[n * D + k] = __float2half_rn(Wq[k * D + n]);
    } else if (bx < 512) {                // Wk^T -> bf16 hi/lo
        int k = bx - 256, n = tid;
        float w = Wk[k * D + n];
        __nv_bfloat16 h = __float2bfloat16(w);
        g_bkh[n * D + k] = h;
        g_bkl[n * D + k] = __float2bfloat16(w - __bfloat162float(h));
    } else {                              // wvsum
        int row  = (bx - 512) * 8 + (tid >> 5);
        int lane = tid & 31;
        float p = 0.f;
        #pragma unroll
        for (int j = lane; j < D; j += 32) p += Wv[row * D + j];
        #pragma unroll
        for (int off = 16; off; off >>= 1) p += __shfl_xor_sync(0xffffffffu, p, off);
        if (lane == 0) g_wvsum[row] = p;
    }
}

// ======================= y kernel: y bf16 split ============================
__global__ void y_kernel(const float* __restrict__ x) {
    __shared__ float xs[Bsz][D];
    __shared__ float vs[Bsz];
    __shared__ float wv[D];
    int t = blockIdx.x;
    int e = threadIdx.x;

    wv[e] = g_wvsum[e];
    #pragma unroll
    for (int b = 0; b < Bsz; ++b)
        xs[b][e] = x[((size_t)b * T + t) * D + e];
    __syncthreads();

    int warp = e >> 5, lane = e & 31;
    #pragma unroll
    for (int rep = 0; rep < 2; ++rep) {
        int b = warp * 2 + rep;
        float p = 0.f;
        #pragma unroll
        for (int k = lane; k < D; k += 32) p += xs[b][k] * wv[k];
        #pragma unroll
        for (int off = 16; off; off >>= 1) p += __shfl_xor_sync(0xffffffffu, p, off);
        if (lane == 0) vs[b] = p;
    }
    __syncthreads();

    float acc = 0.f;
    #pragma unroll
    for (int b = 0; b < Bsz; ++b) acc += vs[b] * xs[b][e];
    __nv_bfloat16 h = __float2bfloat16(acc);
    g_yh[t * D + e] = h;
    g_yl[t * D + e] = __float2bfloat16(acc - __bfloat162float(h));
}

#define ROWB 80

// ======================= cgemm: bf16 3-pass, CTA 32x128 ====================
__global__ void __launch_bounds__(256, 2)
cgemm_mma(const __nv_bfloat16* __restrict__ ah, const __nv_bfloat16* __restrict__ al,
          const __nv_bfloat16* __restrict__ bth, const __nv_bfloat16* __restrict__ btl,
          float* __restrict__ C) {
    __shared__ char sAh[32 * ROWB], sAl[32 * ROWB];
    __shared__ char sBh[128 * ROWB], sBl[128 * ROWB];

    int tid = threadIdx.x, wid = tid >> 5, lane = tid & 31;
    int m0 = blockIdx.x * 32, n0 = blockIdx.y * 128;
    int mwarp = (wid & 1) * 16, nwarp = (wid >> 1) * 32;

    uint32_t uAh = smem_u32(sAh), uAl = smem_u32(sAl);
    uint32_t uBh = smem_u32(sBh), uBl = smem_u32(sBl);

    float acc[4][4] = {};
    int arow = lane & 15, ao16 = (lane >> 4) * 16;
    int brow = lane & 7,  bo16 = ((lane >> 3) & 1) * 16;

    for (int kc = 0; kc < 8; ++kc) {
        __syncthreads();
        for (int i = tid; i < 128; i += 256) {
            int r = i >> 2, c16 = i & 3;
            size_t goff = (size_t)(m0 + r) * 256 + kc * 32 + c16 * 8;
            uint32_t so = r * ROWB + c16 * 16;
            *(uint4*)(sAh + so) = *(const uint4*)(ah + goff);
            *(uint4*)(sAl + so) = *(const uint4*)(al + goff);
        }
        #pragma unroll
        for (int j = 0; j < 2; ++j) {
            int i = tid + j * 256;
            int r = i >> 2, c16 = i & 3;
            size_t goff = (size_t)(n0 + r) * 256 + kc * 32 + c16 * 8;
            uint32_t so = r * ROWB + c16 * 16;
            *(uint4*)(sBh + so) = *(const uint4*)(bth + goff);
            *(uint4*)(sBl + so) = *(const uint4*)(btl + goff);
        }
        __syncthreads();

        #pragma unroll
        for (int pass = 0; pass < 3; ++pass) {
            uint32_t uA = (pass < 2) ? uAh : uAl;
            uint32_t uB = (pass == 1) ? uBl : uBh;
            #pragma unroll
            for (int kk = 0; kk < 2; ++kk) {
                uint32_t af[4], bf[4][2];
                ldm_x4(af, uA + (mwarp + arow) * ROWB + kk * 32 + ao16);
                #pragma unroll
                for (int nf = 0; nf < 4; ++nf)
                    ldm_x2(bf[nf], uB + (nwarp + nf * 8 + brow) * ROWB + kk * 32 + bo16);
                #pragma unroll
                for (int nf = 0; nf < 4; ++nf)
                    mma_bf16(acc[nf], af, bf[nf]);
            }
        }
    }

    int tq = lane >> 2, tr = (lane & 3) * 2;
    #pragma unroll
    for (int half = 0; half < 2; ++half) {
        int m = m0 + mwarp + tq + half * 8;
        size_t obase = (size_t)m * 256;
        #pragma unroll
        for (int nf = 0; nf < 4; ++nf) {
            int n = n0 + nwarp + nf * 8 + tr;
            float2 v;
            v.x = acc[nf][half * 2 + 0];
            v.y = acc[nf][half * 2 + 1];
            *(float2*)(C + obase + n) = v;
        }
    }
}

// ======================= qgemm: fp16 1-pass, reg dbuf, A from fp32 =========
__global__ void __launch_bounds__(256, 2)
qgemm_mma(const float* __restrict__ a32, const __half* __restrict__ bth,
          float* __restrict__ C) {
    __shared__ char sA[2][128 * ROWB];
    __shared__ char sB[2][128 * ROWB];

    int tid = threadIdx.x, wid = tid >> 5, lane = tid & 31;
    int m0 = blockIdx.x * 128, n0 = blockIdx.y * 128;
    int mwarp = (wid & 1) * 64, nwarp = (wid >> 1) * 32;

    uint32_t uA0 = smem_u32(sA[0]), uA1 = smem_u32(sA[1]);
    uint32_t uB0 = smem_u32(sB[0]), uB1 = smem_u32(sB[1]);

    float acc[4][4][4] = {};
    int arow = lane & 15, ao16 = (lane >> 4) * 16;
    int brow = lane & 7,  bo16 = ((lane >> 3) & 1) * 16;

    // per-thread mapping: 2 x (8 halves) for A and B
    int r0 = tid >> 2, c0 = (tid & 3);
    int r1 = (tid + 256) >> 2, c1 = ((tid + 256) & 3);
    uint32_t so0 = r0 * ROWB + c0 * 16, so1 = r1 * ROWB + c1 * 16;

    float4 fa00, fa01, fa10, fa11;   // A fp32: 16 floats
    uint4 rb0, rb1;
    auto ldg = [&](int kc) {
        const float* a0 = a32 + (size_t)(m0 + r0) * 256 + kc * 32 + c0 * 8;
        const float* a1 = a32 + (size_t)(m0 + r1) * 256 + kc * 32 + c1 * 8;
        fa00 = *(const float4*)(a0);
        fa01 = *(const float4*)(a0 + 4);
        fa10 = *(const float4*)(a1);
        fa11 = *(const float4*)(a1 + 4);
        rb0 = *(const uint4*)(bth + (size_t)(n0 + r0) * 256 + kc * 32 + c0 * 8);
        rb1 = *(const uint4*)(bth + (size_t)(n0 + r1) * 256 + kc * 32 + c1 * 8);
    };
    auto sts = [&](int st) {
        uint4 pa0, pa1;
        pa0.x = pack_h2(fa00.x, fa00.y); pa0.y = pack_h2(fa00.z, fa00.w);
        pa0.z = pack_h2(fa01.x, fa01.y); pa0.w = pack_h2(fa01.z, fa01.w);
        pa1.x = pack_h2(fa10.x, fa10.y); pa1.y = pack_h2(fa10.z, fa10.w);
        pa1.z = pack_h2(fa11.x, fa11.y); pa1.w = pack_h2(fa11.z, fa11.w);
        *(uint4*)(sA[st] + so0) = pa0;
        *(uint4*)(sA[st] + so1) = pa1;
        *(uint4*)(sB[st] + so0) = rb0;
        *(uint4*)(sB[st] + so1) = rb1;
    };

    ldg(0);
    sts(0);

    for (int kc = 0; kc < 8; ++kc) {
        __syncthreads();                     // stage kc&1 populated
        if (kc < 7) ldg(kc + 1);             // LDG latency hides under MMA block
        uint32_t uAh = (kc & 1) ? uA1 : uA0;
        uint32_t uBh = (kc & 1) ? uB1 : uB0;

        #pragma unroll
        for (int kk = 0; kk < 2; ++kk) {
            uint32_t af[4][4], bf[4][2];
            #pragma unroll
            for (int mf = 0; mf < 4; ++mf)
                ldm_x4(af[mf], uAh + (mwarp + mf * 16 + arow) * ROWB + kk * 32 + ao16);
            #pragma unroll
            for (int nf = 0; nf < 4; ++nf)
                ldm_x2(bf[nf], uBh + (nwarp + nf * 8 + brow) * ROWB + kk * 32 + bo16);
            #pragma unroll
            for (int mf = 0; mf < 4; ++mf)
                #pragma unroll
                for (int nf = 0; nf < 4; ++nf)
                    mma_fp16(acc[mf][nf], af[mf], bf[nf]);
        }
        __syncthreads();                     // all reads of this stage done
        if (kc < 7) sts((kc + 1) & 1);
    }

    // ---- epilogue: scramble-scale + float2 stores ----
    int tq = lane >> 2, tr = (lane & 3) * 2;
    #pragma unroll
    for (int mf = 0; mf < 4; ++mf) {
        #pragma unroll
        for (int half = 0; half < 2; ++half) {
            int m = m0 + mwarp + mf * 16 + tq + half * 8;
            size_t obase = (size_t)m * 256;
            int q = m & (T - 1);
            int qh = q >> 8, qc = q & 255;
            #pragma unroll
            for (int nf = 0; nf < 4; ++nf) {
                int n = n0 + nwarp + nf * 8 + tr;
                float s0 = g_S[(((n + 0) << 3) + qh) * 256 + qc];
                float s1 = g_S[(((n + 1) << 3) + qh) * 256 + qc];
                float2 v;
                v.x = acc[mf][nf][half * 2 + 0] * s0;
                v.y = acc[mf][nf][half * 2 + 1] * s1;
                *(float2*)(C + obase + n) = v;
            }
        }
    }
}

// ======================= exact 2-phase scan ================================
__global__ void scanA_kernel() {
    int d = threadIdx.x, g = blockIdx.x;
    int t0 = g * LTILE;
    float s = 0.f;
    #pragma unroll
    for (int i = 0; i < LTILE; ++i) {
        int t = t0 + i;
        float cv = (t == 0) ? 0.f : g_c[t * D + d];
        s = 0.9f * s + cv;
        g_S[t * D + d] = s;
    }
    g_carry[g * D + d] = s;
}
// each CTA g reconstructs its incoming carry from g_carry[0..g-1], then fixes
// up its tile. carry array (256KB) is L2-resident and broadcast across CTAs.
__global__ void scanBC_kernel() {
    int d = threadIdx.x, g = blockIdx.x;
    int t0 = g * LTILE;
    if (g == 0) {
        g_S[d] = g_S[D + d];    // S[0] = r[1]
        return;
    }
    float carry = 0.f;
    for (int j = 0; j < g; ++j)
        carry = fmaf(GL, carry, g_carry[j * D + d]);
    float p = 0.9f;
    #pragma unroll
    for (int i = 0; i < LTILE; ++i) {
        g_S[(t0 + i) * D + d] += p * carry;
        p *= 0.9f;
    }
}

// ======================= launch ============================================
extern "C" void kernel_launch(void* const* d_in, const int* in_sizes, int n_in,
                              void* d_out, int out_size) {
    const float* x  = (const float*)d_in[0];
    const float* Wq = (const float*)d_in[1];
    const float* Wk = (const float*)d_in[2];
    const float* Wv = (const float*)d_in[3];
    float* out = (float*)d_out;

    float* c_p; cudaGetSymbolAddress((void**)&c_p, g_c);
    __nv_bfloat16* yh_p; cudaGetSymbolAddress((void**)&yh_p, g_yh);
    __nv_bfloat16* yl_p; cudaGetSymbolAddress((void**)&yl_p, g_yl);
    __half* wqh_p; cudaGetSymbolAddress((void**)&wqh_p, g_wqh);
    __nv_bfloat16* bkh_p; cudaGetSymbolAddress((void**)&bkh_p, g_bkh);
    __nv_bfloat16* bkl_p; cudaGetSymbolAddress((void**)&bkl_p, g_bkl);

    prep_kernel<<<544, 256>>>(Wq, Wk, Wv);
    y_kernel<<<T, 256>>>(x);
    {
        dim3 grid(T / 32, 2);                 // c = y @ Wk  (128 CTAs)
        cgemm_mma<<<grid, 256>>>(yh_p, yl_p, bkh_p, bkl_p, c_p);
    }
    scanA_kernel<<<NTILE, 256>>>();
    scanBC_kernel<<<NTILE, 256>>>();
    {
        dim3 grid((Bsz * T) / 128, 2);        // out = scramble(S) * (x @ Wq)
        qgemm_mma<<<grid, 256>>>(x, wqh_p, out);
    }
}